// round 3
// baseline (speedup 1.0000x reference)
#include <cuda_runtime.h>
#include <math.h>

#define N_MET 250000
#define N_RXN 500000
#define E_SUB 2000000
#define E_ALL 4000000
#define DT    0.01f
#define NB1   489   /* ceil(N_RXN/1024) */
#define G     128   /* interpolation grid */

// ---------------- constant weights ----------------
__constant__ float cW1[128];   // [2][64]
__constant__ float cb1[64];
__constant__ float cW2[2048];  // [64][32]
__constant__ float cb2[32];
__constant__ float cW3[2048];  // [32][64]
__constant__ float cb3[64];
__constant__ float cW4[64];
__constant__ float cb4c[1];

// ---------------- device scratch ----------------
__device__ float g_conc[N_MET];
__device__ float g_total[N_MET];
__device__ float g_met_scale[N_MET];
__device__ int   g_count[N_RXN];
__device__ int   g_offset[N_RXN + 1];
__device__ int   g_cursor[N_RXN];
__device__ int   g_bsum[NB1];
__device__ int   g_bofs[NB1];
__device__ float g_perm_c[E_SUB];
__device__ float g_perm_s[E_SUB];
__device__ int   g_perm_met[E_SUB];
__device__ float g_v[N_RXN];
// msg table: [ic][is][32] = tanh([c,s]@W1 + b1) @ W2   (b2 excluded; added via count)
__device__ float g_tab[G * G * 32];

__device__ __forceinline__ float tanh1(float x) {
    float e = __expf(2.0f * x);
    return 1.0f - __fdividef(2.0f, e + 1.0f);
}

// ---------------- init ----------------
__global__ void k_init(const float* __restrict__ x, float* __restrict__ out) {
    int i = blockIdx.x * blockDim.x + threadIdx.x;
    if (i < N_MET) {
        g_conc[i]  = x[i * 8 + 3];
        g_total[i] = 0.0f;
        out[i]     = 0.0f;
    }
    if (i < N_RXN) g_count[i] = 0;
}

// ---------------- build msg interpolation table ----------------
__global__ void k_tab() {
    int idx = blockIdx.x * blockDim.x + threadIdx.x;
    if (idx >= G * G) return;
    int ic = idx / G, is_ = idx % G;
    float c = (float)ic * (1.0f / (G - 1));
    float s = 0.5f + (float)is_ * (1.0f / (G - 1));
    float m[32];
#pragma unroll
    for (int k = 0; k < 32; k++) m[k] = 0.0f;
    for (int j = 0; j < 64; ++j) {
        float t = tanhf(fmaf(c, cW1[j], fmaf(s, cW1[64 + j], cb1[j])));
#pragma unroll
        for (int k = 0; k < 32; k++) m[k] = fmaf(t, cW2[j * 32 + k], m[k]);
    }
    float* dst = &g_tab[idx * 32];
#pragma unroll
    for (int k = 0; k < 32; k++) dst[k] = m[k];
}

// ---------------- CSR build ----------------
__global__ void k_hist(const int* __restrict__ rxn_sub) {
    int e = blockIdx.x * blockDim.x + threadIdx.x;
    if (e < E_SUB) atomicAdd(&g_count[rxn_sub[e]], 1);
}

__global__ void k_scan_partial() {
    __shared__ int sh[1024];
    int t = threadIdx.x;
    int i = blockIdx.x * 1024 + t;
    sh[t] = (i < N_RXN) ? g_count[i] : 0;
    __syncthreads();
    for (int s = 512; s > 0; s >>= 1) {
        if (t < s) sh[t] += sh[t + s];
        __syncthreads();
    }
    if (t == 0) g_bsum[blockIdx.x] = sh[0];
}

__global__ void k_scan_bsum() {
    __shared__ int sh[512];
    int t = threadIdx.x;
    int vorig = (t < NB1) ? g_bsum[t] : 0;
    sh[t] = vorig;
    __syncthreads();
    for (int off = 1; off < 512; off <<= 1) {
        int add = (t >= off) ? sh[t - off] : 0;
        __syncthreads();
        sh[t] += add;
        __syncthreads();
    }
    if (t < NB1) g_bofs[t] = sh[t] - vorig;
}

__global__ void k_scan_final() {
    __shared__ int sh[1024];
    int t = threadIdx.x;
    int i = blockIdx.x * 1024 + t;
    int c = (i < N_RXN) ? g_count[i] : 0;
    sh[t] = c;
    __syncthreads();
    for (int off = 1; off < 1024; off <<= 1) {
        int add = (t >= off) ? sh[t - off] : 0;
        __syncthreads();
        sh[t] += add;
        __syncthreads();
    }
    if (i < N_RXN) {
        int base = g_bofs[blockIdx.x];
        int excl = base + sh[t] - c;
        g_offset[i] = excl;
        g_cursor[i] = excl;
        if (i == N_RXN - 1) g_offset[N_RXN] = base + sh[t];
    }
}

__global__ void k_scatter(const int* __restrict__ met_sub,
                          const int* __restrict__ rxn_sub,
                          const float* __restrict__ sto_sub) {
    int e = blockIdx.x * blockDim.x + threadIdx.x;
    if (e >= E_SUB) return;
    int r = rxn_sub[e];
    int m = met_sub[e];
    int p = atomicAdd(&g_cursor[r], 1);
    g_perm_c[p]   = g_conc[m];
    g_perm_s[p]   = sto_sub[e];
    g_perm_met[p] = m;
}

// ---------------- fused per-reaction: table-interp + MLP + consumption ----------------
__global__ void __launch_bounds__(256) k_rxn(const float* __restrict__ log_k) {
    int r = blockIdx.x * blockDim.x + threadIdx.x;
    if (r >= N_RXN) return;
    int beg = g_offset[r];
    int end = g_offset[r + 1];
    float n = (float)(end - beg);

    float h[32];
#pragma unroll
    for (int k = 0; k < 32; k++) h[k] = 0.0f;

    for (int i = beg; i < end; ++i) {
        float c = g_perm_c[i];
        float s = g_perm_s[i];
        float fc = fminf(fmaxf(c, 0.0f), 1.0f) * (float)(G - 1);
        float fs = (fminf(fmaxf(s, 0.5f), 1.5f) - 0.5f) * (float)(G - 1);
        int ic  = min((int)fc, G - 2);
        int is_ = min((int)fs, G - 2);
        float wc = fc - (float)ic;
        float ws = fs - (float)is_;
        float w00 = (1.0f - wc) * (1.0f - ws);
        float w01 = (1.0f - wc) * ws;
        float w10 = wc * (1.0f - ws);
        float w11 = wc * ws;
        const float4* p0 = (const float4*)&g_tab[(ic * G + is_) * 32];        // (ic,is), (ic,is+1) at +8
        const float4* p1 = (const float4*)&g_tab[((ic + 1) * G + is_) * 32];  // (ic+1,is), (ic+1,is+1) at +8
#pragma unroll
        for (int q = 0; q < 8; q++) {
            float4 a  = __ldg(p0 + q);
            float4 b  = __ldg(p0 + q + 8);
            float4 d  = __ldg(p1 + q);
            float4 e4 = __ldg(p1 + q + 8);
            h[4 * q + 0] += w00 * a.x + w01 * b.x + w10 * d.x + w11 * e4.x;
            h[4 * q + 1] += w00 * a.y + w01 * b.y + w10 * d.y + w11 * e4.y;
            h[4 * q + 2] += w00 * a.z + w01 * b.z + w10 * d.z + w11 * e4.z;
            h[4 * q + 3] += w00 * a.w + w01 * b.w + w10 * d.w + w11 * e4.w;
        }
    }
#pragma unroll
    for (int k = 0; k < 32; k++) h[k] = fmaf(n, cb2[k], h[k]);

    float racc = cb4c[0];
    for (int j = 0; j < 64; ++j) {
        float a = cb3[j];
#pragma unroll
        for (int k = 0; k < 32; k++) a = fmaf(h[k], cW3[k * 64 + j], a);
        racc = fmaf(tanh1(a), cW4[j], racc);
    }

    float sp = fmaxf(racc, 0.0f) + log1pf(__expf(-fabsf(racc)));
    float kk = __expf(log_k[r] * 2.302585093f);
    float v = kk * sp;
    g_v[r] = v;

    // fused consumption scatter (was k_total)
    float vdt = v * DT;
    for (int i = beg; i < end; ++i) {
        atomicAdd(&g_total[g_perm_met[i]], g_perm_s[i] * vdt);
    }
}

__global__ void k_metscale() {
    int i = blockIdx.x * blockDim.x + threadIdx.x;
    if (i >= N_MET) return;
    float t = g_total[i];
    float c = g_conc[i];
    g_met_scale[i] = (t > 1e-12f) ? fminf(c / t, 1.0f) : 1.0f;
}

__global__ void k_vscale() {
    int r = blockIdx.x * blockDim.x + threadIdx.x;
    if (r >= N_RXN) return;
    int beg = g_offset[r];
    int end = g_offset[r + 1];
    float m = 1.0f;
    for (int i = beg; i < end; ++i) m = fminf(m, g_met_scale[g_perm_met[i]]);
    g_v[r] *= m;
}

__global__ void k_out(const int* __restrict__ met_all,
                      const int* __restrict__ rxn_all,
                      const float* __restrict__ sto_all,
                      float* __restrict__ out) {
    int e = blockIdx.x * blockDim.x + threadIdx.x;
    if (e >= E_ALL) return;
    float contrib = sto_all[e] * g_v[rxn_all[e]];
    atomicAdd(&out[met_all[e]], contrib);
}

extern "C" void kernel_launch(void* const* d_in, const int* in_sizes, int n_in,
                              void* d_out, int out_size) {
    const float* x       = (const float*)d_in[0];
    const int*   met_sub = (const int*)d_in[1];
    const int*   rxn_sub = (const int*)d_in[2];
    const float* sto_sub = (const float*)d_in[3];
    const int*   met_all = (const int*)d_in[4];
    const int*   rxn_all = (const int*)d_in[5];
    const float* sto_all = (const float*)d_in[6];
    const float* log_k   = (const float*)d_in[15];
    float* out = (float*)d_out;

    cudaMemcpyToSymbolAsync(cW1,  d_in[7],  128  * sizeof(float), 0, cudaMemcpyDeviceToDevice, 0);
    cudaMemcpyToSymbolAsync(cb1,  d_in[8],  64   * sizeof(float), 0, cudaMemcpyDeviceToDevice, 0);
    cudaMemcpyToSymbolAsync(cW2,  d_in[9],  2048 * sizeof(float), 0, cudaMemcpyDeviceToDevice, 0);
    cudaMemcpyToSymbolAsync(cb2,  d_in[10], 32   * sizeof(float), 0, cudaMemcpyDeviceToDevice, 0);
    cudaMemcpyToSymbolAsync(cW3,  d_in[11], 2048 * sizeof(float), 0, cudaMemcpyDeviceToDevice, 0);
    cudaMemcpyToSymbolAsync(cb3,  d_in[12], 64   * sizeof(float), 0, cudaMemcpyDeviceToDevice, 0);
    cudaMemcpyToSymbolAsync(cW4,  d_in[13], 64   * sizeof(float), 0, cudaMemcpyDeviceToDevice, 0);
    cudaMemcpyToSymbolAsync(cb4c, d_in[14], 1    * sizeof(float), 0, cudaMemcpyDeviceToDevice, 0);

    k_init<<<(N_RXN + 255) / 256, 256>>>(x, out);
    k_tab<<<(G * G + 255) / 256, 256>>>();
    k_hist<<<(E_SUB + 255) / 256, 256>>>(rxn_sub);
    k_scan_partial<<<NB1, 1024>>>();
    k_scan_bsum<<<1, 512>>>();
    k_scan_final<<<NB1, 1024>>>();
    k_scatter<<<(E_SUB + 255) / 256, 256>>>(met_sub, rxn_sub, sto_sub);
    k_rxn<<<(N_RXN + 255) / 256, 256>>>(log_k);
    k_metscale<<<(N_MET + 255) / 256, 256>>>();
    k_vscale<<<(N_RXN + 255) / 256, 256>>>();
    k_out<<<(E_ALL + 255) / 256, 256>>>(met_all, rxn_all, sto_all, out);
}

// round 4
// speedup vs baseline: 1.8618x; 1.8618x over previous
#include <cuda_runtime.h>
#include <math.h>

#define N_MET 250000
#define N_RXN 500000
#define E_SUB 2000000
#define E_ALL 4000000
#define DT    0.01f
#define NB1   489   /* ceil(N_RXN/1024) */

// ---------------- constant weights ----------------
__constant__ float cW1[128];   // [2][64]: cW1[j]=W1[0][j] (conc), cW1[64+j]=W1[1][j] (sto)
__constant__ float cb1[64];
__constant__ float cW2[2048];  // [64][32]
__constant__ float cb2[32];
__constant__ float cW3[2048];  // [32][64]
__constant__ float cb3[64];
__constant__ float cW4[64];
__constant__ float cb4c[1];

// ---------------- device scratch (zero-initialized at load) ----------------
__device__ float  g_conc[N_MET];
__device__ float  g_total[N_MET];       // reset by k_metscale each run
__device__ float  g_met_scale[N_MET];
__device__ int    g_count[N_RXN];       // reset by k_scan_final each run
__device__ int    g_offset[N_RXN + 1];
__device__ int    g_cursor[N_RXN];
__device__ int    g_bsum[NB1];
__device__ int    g_bofs[NB1];
__device__ float2 g_perm_cs[E_SUB];     // (conc, sto) reaction-grouped
__device__ int    g_perm_met[E_SUB];
__device__ float  g_v[N_RXN];

__device__ __forceinline__ float tanha(float x) {
    float t;
    asm("tanh.approx.f32 %0, %1;" : "=f"(t) : "f"(x));
    return t;
}

// ---------------- launch 0: histogram + conc/out init ----------------
__global__ void k_hist(const int* __restrict__ rxn_sub,
                       const float* __restrict__ x,
                       float* __restrict__ out) {
    int e = blockIdx.x * blockDim.x + threadIdx.x;
    if (e < N_MET) {
        g_conc[e] = x[e * 8 + 3];
        out[e]    = 0.0f;
    }
    if (e < E_SUB) atomicAdd(&g_count[rxn_sub[e]], 1);
}

// ---------------- launch 1-3: CSR scan ----------------
__global__ void k_scan_partial() {
    __shared__ int sh[1024];
    int t = threadIdx.x;
    int i = blockIdx.x * 1024 + t;
    sh[t] = (i < N_RXN) ? g_count[i] : 0;
    __syncthreads();
    for (int s = 512; s > 0; s >>= 1) {
        if (t < s) sh[t] += sh[t + s];
        __syncthreads();
    }
    if (t == 0) g_bsum[blockIdx.x] = sh[0];
}

__global__ void k_scan_bsum() {
    __shared__ int sh[512];
    int t = threadIdx.x;
    int vorig = (t < NB1) ? g_bsum[t] : 0;
    sh[t] = vorig;
    __syncthreads();
    for (int off = 1; off < 512; off <<= 1) {
        int add = (t >= off) ? sh[t - off] : 0;
        __syncthreads();
        sh[t] += add;
        __syncthreads();
    }
    if (t < NB1) g_bofs[t] = sh[t] - vorig;
}

__global__ void k_scan_final() {
    __shared__ int sh[1024];
    int t = threadIdx.x;
    int i = blockIdx.x * 1024 + t;
    int c = (i < N_RXN) ? g_count[i] : 0;
    sh[t] = c;
    __syncthreads();
    for (int off = 1; off < 1024; off <<= 1) {
        int add = (t >= off) ? sh[t - off] : 0;
        __syncthreads();
        sh[t] += add;
        __syncthreads();
    }
    if (i < N_RXN) {
        int base = g_bofs[blockIdx.x];
        int excl = base + sh[t] - c;
        g_offset[i] = excl;
        g_cursor[i] = excl;
        g_count[i]  = 0;                 // self-reset for next replay
        if (i == N_RXN - 1) g_offset[N_RXN] = base + sh[t];
    }
}

// ---------------- launch 4: scatter into reaction-grouped arrays ----------------
__global__ void k_scatter(const int* __restrict__ met_sub,
                          const int* __restrict__ rxn_sub,
                          const float* __restrict__ sto_sub) {
    int e = blockIdx.x * blockDim.x + threadIdx.x;
    if (e >= E_SUB) return;
    int r = rxn_sub[e];
    int m = met_sub[e];
    int p = atomicAdd(&g_cursor[r], 1);
    g_perm_cs[p]  = make_float2(g_conc[m], sto_sub[e]);
    g_perm_met[p] = m;
}

// ---------------- launch 5 (ncu-captured): fused per-reaction MLP + consumption ----------------
__global__ void __launch_bounds__(256) k_rxn(const float* __restrict__ log_k) {
    int r = blockIdx.x * blockDim.x + threadIdx.x;
    if (r >= N_RXN) return;
    int beg = g_offset[r];
    int end = g_offset[r + 1];
    float n = (float)(end - beg);

    float h[32];
#pragma unroll
    for (int k = 0; k < 32; k++) h[k] = n * cb2[k];

    // hidden dim in 4 chunks of 16 (T regs statically indexed; chunk loop dynamic)
    for (int jc = 0; jc < 4; ++jc) {
        int jb = jc * 16;
        float T[16];
#pragma unroll
        for (int j = 0; j < 16; j++) T[j] = 0.0f;
        for (int i = beg; i < end; ++i) {
            float2 cs = g_perm_cs[i];
#pragma unroll
            for (int j = 0; j < 16; j++) {
                float z = fmaf(cs.x, cW1[jb + j], fmaf(cs.y, cW1[64 + jb + j], cb1[jb + j]));
                T[j] += tanha(z);
            }
        }
#pragma unroll
        for (int j = 0; j < 16; j++) {
            float t = T[j];
            const float* w2 = &cW2[(jb + j) * 32];
#pragma unroll
            for (int k = 0; k < 32; k++) h[k] = fmaf(t, w2[k], h[k]);
        }
    }

    float racc = cb4c[0];
    for (int j = 0; j < 64; ++j) {
        float a = cb3[j];
#pragma unroll
        for (int k = 0; k < 32; k++) a = fmaf(h[k], cW3[k * 64 + j], a);
        racc = fmaf(tanha(a), cW4[j], racc);
    }

    // v = 10^log_k * softplus(racc)
    float sp = fmaxf(racc, 0.0f) + log1pf(__expf(-fabsf(racc)));
    float kk = __expf(log_k[r] * 2.302585093f);
    float v = kk * sp;
    g_v[r] = v;

    // fused consumption scatter
    float vdt = v * DT;
    for (int i = beg; i < end; ++i) {
        atomicAdd(&g_total[g_perm_met[i]], g_perm_cs[i].y * vdt);
    }
}

// ---------------- launch 6: per-metabolite scale (+ total reset) ----------------
__global__ void k_metscale() {
    int i = blockIdx.x * blockDim.x + threadIdx.x;
    if (i >= N_MET) return;
    float t = g_total[i];
    float c = g_conc[i];
    g_met_scale[i] = (t > 1e-12f) ? fminf(c / t, 1.0f) : 1.0f;
    g_total[i] = 0.0f;                   // self-reset for next replay
}

// ---------------- launch 7: per-reaction min scale ----------------
__global__ void k_vscale() {
    int r = blockIdx.x * blockDim.x + threadIdx.x;
    if (r >= N_RXN) return;
    int beg = g_offset[r];
    int end = g_offset[r + 1];
    float m = 1.0f;
    for (int i = beg; i < end; ++i) m = fminf(m, g_met_scale[g_perm_met[i]]);
    g_v[r] *= m;
}

// ---------------- launch 8: final scatter into dxdt ----------------
__global__ void k_out(const int* __restrict__ met_all,
                      const int* __restrict__ rxn_all,
                      const float* __restrict__ sto_all,
                      float* __restrict__ out) {
    int e = blockIdx.x * blockDim.x + threadIdx.x;
    if (e >= E_ALL) return;
    float contrib = sto_all[e] * g_v[rxn_all[e]];
    atomicAdd(&out[met_all[e]], contrib);
}

extern "C" void kernel_launch(void* const* d_in, const int* in_sizes, int n_in,
                              void* d_out, int out_size) {
    const float* x       = (const float*)d_in[0];
    const int*   met_sub = (const int*)d_in[1];
    const int*   rxn_sub = (const int*)d_in[2];
    const float* sto_sub = (const float*)d_in[3];
    const int*   met_all = (const int*)d_in[4];
    const int*   rxn_all = (const int*)d_in[5];
    const float* sto_all = (const float*)d_in[6];
    const float* log_k   = (const float*)d_in[15];
    float* out = (float*)d_out;

    cudaMemcpyToSymbolAsync(cW1,  d_in[7],  128  * sizeof(float), 0, cudaMemcpyDeviceToDevice, 0);
    cudaMemcpyToSymbolAsync(cb1,  d_in[8],  64   * sizeof(float), 0, cudaMemcpyDeviceToDevice, 0);
    cudaMemcpyToSymbolAsync(cW2,  d_in[9],  2048 * sizeof(float), 0, cudaMemcpyDeviceToDevice, 0);
    cudaMemcpyToSymbolAsync(cb2,  d_in[10], 32   * sizeof(float), 0, cudaMemcpyDeviceToDevice, 0);
    cudaMemcpyToSymbolAsync(cW3,  d_in[11], 2048 * sizeof(float), 0, cudaMemcpyDeviceToDevice, 0);
    cudaMemcpyToSymbolAsync(cb3,  d_in[12], 64   * sizeof(float), 0, cudaMemcpyDeviceToDevice, 0);
    cudaMemcpyToSymbolAsync(cW4,  d_in[13], 64   * sizeof(float), 0, cudaMemcpyDeviceToDevice, 0);
    cudaMemcpyToSymbolAsync(cb4c, d_in[14], 1    * sizeof(float), 0, cudaMemcpyDeviceToDevice, 0);

    k_hist        <<<(E_SUB + 255) / 256, 256>>>(rxn_sub, x, out);   // 0
    k_scan_partial<<<NB1, 1024>>>();                                 // 1
    k_scan_bsum   <<<1, 512>>>();                                    // 2
    k_scan_final  <<<NB1, 1024>>>();                                 // 3
    k_scatter     <<<(E_SUB + 255) / 256, 256>>>(met_sub, rxn_sub, sto_sub); // 4
    k_rxn         <<<(N_RXN + 255) / 256, 256>>>(log_k);             // 5 <- ncu -s 5
    k_metscale    <<<(N_MET + 255) / 256, 256>>>();                  // 6
    k_vscale      <<<(N_RXN + 255) / 256, 256>>>();                  // 7
    k_out         <<<(E_ALL + 255) / 256, 256>>>(met_all, rxn_all, sto_all, out); // 8
}

// round 5
// speedup vs baseline: 3.9654x; 2.1298x over previous
#include <cuda_runtime.h>
#include <math.h>
#include <stdint.h>

#define N_MET 250000
#define N_RXN 500000
#define E_SUB 2000000
#define E_ALL 4000000
#define DT    0.01f
#define NB1   489   /* ceil(N_RXN/1024) */

// ---------------- constant weights (16B aligned for paired loads) ----------------
__constant__ __align__(16) float cW1[128];   // [2][64]: [j]=W1[0][j] (conc), [64+j]=W1[1][j] (sto)
__constant__ __align__(16) float cb1[64];
__constant__ __align__(16) float cW2[2048];  // [64][32]
__constant__ __align__(16) float cb2[32];
__constant__ __align__(16) float cW3[2048];  // [32][64]
__constant__ __align__(16) float cb3[64];
__constant__ __align__(16) float cW4[64];
__constant__ __align__(16) float cb4c[1];

// ---------------- device scratch (zero at module load) ----------------
__device__ float  g_conc[N_MET];
__device__ float  g_total[N_MET];                 // reset by k_metscale
__device__ float  g_met_scale[N_MET];
__device__ int    g_count[N_RXN];                 // reset by k_scan
__device__ int    g_offset[N_RXN + 1];
__device__ int    g_cursor[N_RXN];
__device__ int    g_ticket;                       // reset by k_hist
__device__ volatile unsigned long long g_pack[NB1]; // (val<<2)|status, reset by k_hist
__device__ float4 g_perm[E_SUB];                  // (conc, sto, met-as-float-bits, 0)
__device__ float  g_v[N_RXN];

// ---------------- helpers ----------------
__device__ __forceinline__ float tanha(float x) {
    float t; asm("tanh.approx.f32 %0, %1;" : "=f"(t) : "f"(x)); return t;
}
__device__ __forceinline__ uint64_t pk2(float lo, float hi) {
    uint64_t r; asm("mov.b64 %0, {%1, %2};" : "=l"(r) : "f"(lo), "f"(hi)); return r;
}
__device__ __forceinline__ void upk2(float& lo, float& hi, uint64_t v) {
    asm("mov.b64 {%0, %1}, %2;" : "=f"(lo), "=f"(hi) : "l"(v));
}
__device__ __forceinline__ uint64_t fma2(uint64_t a, uint64_t b, uint64_t c) {
    uint64_t d; asm("fma.rn.f32x2 %0, %1, %2, %3;" : "=l"(d) : "l"(a), "l"(b), "l"(c)); return d;
}
__device__ __forceinline__ uint64_t add2(uint64_t a, uint64_t b) {
    uint64_t d; asm("add.rn.f32x2 %0, %1, %2;" : "=l"(d) : "l"(a), "l"(b)); return d;
}
__device__ __forceinline__ uint64_t mul2(uint64_t a, uint64_t b) {
    uint64_t d; asm("mul.rn.f32x2 %0, %1, %2;" : "=l"(d) : "l"(a), "l"(b)); return d;
}
__device__ __forceinline__ uint64_t cpair(const float* p) {   // uniform 64-bit const load
    return *reinterpret_cast<const uint64_t*>(p);
}

// ---------------- launch 0: histogram + init/reset ----------------
__global__ void k_hist(const int* __restrict__ rxn_sub,
                       const float* __restrict__ x,
                       float* __restrict__ out) {
    int e = blockIdx.x * blockDim.x + threadIdx.x;
    if (e == 0) g_ticket = 0;
    if (e < NB1) g_pack[e] = 0ull;
    if (e < N_MET) {
        g_conc[e] = x[e * 8 + 3];
        out[e]    = 0.0f;
    }
    if (e < E_SUB) atomicAdd(&g_count[rxn_sub[e]], 1);
}

// ---------------- launch 1: single-pass decoupled-lookback scan ----------------
__global__ void k_scan() {
    __shared__ int sh[1024];
    __shared__ int s_bid;
    __shared__ int s_prefix;
    int t = threadIdx.x;
    if (t == 0) s_bid = atomicAdd(&g_ticket, 1);
    __syncthreads();
    int bid = s_bid;
    int i = bid * 1024 + t;
    int c = (i < N_RXN) ? g_count[i] : 0;
    sh[t] = c;
    __syncthreads();
    for (int off = 1; off < 1024; off <<= 1) {
        int add = (t >= off) ? sh[t - off] : 0;
        __syncthreads();
        sh[t] += add;
        __syncthreads();
    }
    if (t == 0) {
        int total = sh[1023];
        if (bid == 0) {
            g_pack[0] = (((unsigned long long)total) << 2) | 2ull;
            s_prefix = 0;
        } else {
            g_pack[bid] = (((unsigned long long)total) << 2) | 1ull;
            int ex = 0;
            int p = bid - 1;
            while (true) {
                unsigned long long v;
                do { v = g_pack[p]; } while ((v & 3ull) == 0ull);
                ex += (int)(v >> 2);
                if ((v & 3ull) == 2ull) break;
                --p;
            }
            g_pack[bid] = (((unsigned long long)(ex + total)) << 2) | 2ull;
            s_prefix = ex;
        }
    }
    __syncthreads();
    if (i < N_RXN) {
        int excl = s_prefix + sh[t] - c;
        g_offset[i] = excl;
        g_cursor[i] = excl;
        g_count[i]  = 0;                    // reset for next replay
        if (i == N_RXN - 1) g_offset[N_RXN] = excl + c;
    }
}

// ---------------- launch 2: scatter edges into reaction-grouped float4 records ----------------
__global__ void k_scatter(const int* __restrict__ met_sub,
                          const int* __restrict__ rxn_sub,
                          const float* __restrict__ sto_sub) {
    int e = blockIdx.x * blockDim.x + threadIdx.x;
    if (e >= E_SUB) return;
    int r = rxn_sub[e];
    int m = met_sub[e];
    int p = atomicAdd(&g_cursor[r], 1);
    g_perm[p] = make_float4(g_conc[m], sto_sub[e], __int_as_float(m), 0.0f);
}

// ---------------- launch 3 (ncu-captured): fused per-reaction MLP + consumption ----------------
__global__ void __launch_bounds__(128) k_rxn(const float* __restrict__ log_k) {
    int r = blockIdx.x * blockDim.x + threadIdx.x;
    if (r >= N_RXN) return;
    int beg = g_offset[r];
    int end = g_offset[r + 1];
    float n = (float)(end - beg);

    // ---- phase 2a: Tsum[64] over edges (packed pairs) ----
    uint64_t T2[32];
#pragma unroll
    for (int p = 0; p < 32; p++) T2[p] = 0ull;   // (0.0f, 0.0f)

    for (int i = beg; i < end; ++i) {
        float4 ed = __ldg(&g_perm[i]);
        uint64_t c2 = pk2(ed.x, ed.x);
        uint64_t s2 = pk2(ed.y, ed.y);
#pragma unroll
        for (int p = 0; p < 32; p++) {
            uint64_t z2 = fma2(s2, cpair(&cW1[64 + 2 * p]), cpair(&cb1[2 * p]));
            z2 = fma2(c2, cpair(&cW1[2 * p]), z2);
            float z0, z1; upk2(z0, z1, z2);
            T2[p] = add2(T2[p], pk2(tanha(z0), tanha(z1)));
        }
    }

    // ---- phase 2b: h[32] = Tsum @ W2 + n*b2 (packed) ----
    uint64_t n2 = pk2(n, n);
    uint64_t h2[16];
#pragma unroll
    for (int q = 0; q < 16; q++) h2[q] = mul2(n2, cpair(&cb2[2 * q]));
#pragma unroll
    for (int p = 0; p < 32; p++) {
        float ta, tb; upk2(ta, tb, T2[p]);
        uint64_t ta2 = pk2(ta, ta), tb2 = pk2(tb, tb);
#pragma unroll
        for (int q = 0; q < 16; q++) {
            h2[q] = fma2(ta2, cpair(&cW2[(2 * p) * 32 + 2 * q]), h2[q]);
            h2[q] = fma2(tb2, cpair(&cW2[(2 * p + 1) * 32 + 2 * q]), h2[q]);
        }
    }

    // ---- phase 3: a[64] = tanh(h @ W3 + b3); racc = a @ W4 + b4 (packed) ----
    uint64_t a2[32];
#pragma unroll
    for (int p = 0; p < 32; p++) a2[p] = cpair(&cb3[2 * p]);
#pragma unroll
    for (int q = 0; q < 16; q++) {
        float ha, hb; upk2(ha, hb, h2[q]);
        uint64_t ha2 = pk2(ha, ha), hb2 = pk2(hb, hb);
#pragma unroll
        for (int p = 0; p < 32; p++) {
            a2[p] = fma2(ha2, cpair(&cW3[(2 * q) * 64 + 2 * p]), a2[p]);
            a2[p] = fma2(hb2, cpair(&cW3[(2 * q + 1) * 64 + 2 * p]), a2[p]);
        }
    }
    float racc = cb4c[0];
#pragma unroll
    for (int p = 0; p < 32; p++) {
        float a0, a1; upk2(a0, a1, a2[p]);
        racc = fmaf(tanha(a0), cW4[2 * p], racc);
        racc = fmaf(tanha(a1), cW4[2 * p + 1], racc);
    }

    // v = 10^log_k * softplus(racc)
    float sp = fmaxf(racc, 0.0f) + log1pf(__expf(-fabsf(racc)));
    float kk = __expf(log_k[r] * 2.302585093f);
    float v = kk * sp;
    g_v[r] = v;

    // fused consumption scatter (edge records are L1-hot)
    float vdt = v * DT;
    for (int i = beg; i < end; ++i) {
        float4 ed = g_perm[i];
        atomicAdd(&g_total[__float_as_int(ed.z)], ed.y * vdt);
    }
}

// ---------------- launch 4: per-metabolite scale (+ reset) ----------------
__global__ void k_metscale() {
    int i = blockIdx.x * blockDim.x + threadIdx.x;
    if (i >= N_MET) return;
    float t = g_total[i];
    float c = g_conc[i];
    g_met_scale[i] = (t > 1e-12f) ? fminf(c / t, 1.0f) : 1.0f;
    g_total[i] = 0.0f;                               // reset for next replay
}

// ---------------- launch 5: per-reaction min scale ----------------
__global__ void k_vscale() {
    int r = blockIdx.x * blockDim.x + threadIdx.x;
    if (r >= N_RXN) return;
    int beg = g_offset[r];
    int end = g_offset[r + 1];
    float m = 1.0f;
    for (int i = beg; i < end; ++i)
        m = fminf(m, g_met_scale[__float_as_int(g_perm[i].z)]);
    g_v[r] *= m;
}

// ---------------- launch 6: final scatter into dxdt ----------------
__global__ void k_out(const int* __restrict__ met_all,
                      const int* __restrict__ rxn_all,
                      const float* __restrict__ sto_all,
                      float* __restrict__ out) {
    int e = blockIdx.x * blockDim.x + threadIdx.x;
    if (e >= E_ALL) return;
    float contrib = sto_all[e] * __ldg(&g_v[rxn_all[e]]);
    atomicAdd(&out[met_all[e]], contrib);
}

extern "C" void kernel_launch(void* const* d_in, const int* in_sizes, int n_in,
                              void* d_out, int out_size) {
    const float* x       = (const float*)d_in[0];
    const int*   met_sub = (const int*)d_in[1];
    const int*   rxn_sub = (const int*)d_in[2];
    const float* sto_sub = (const float*)d_in[3];
    const int*   met_all = (const int*)d_in[4];
    const int*   rxn_all = (const int*)d_in[5];
    const float* sto_all = (const float*)d_in[6];
    const float* log_k   = (const float*)d_in[15];
    float* out = (float*)d_out;

    cudaMemcpyToSymbolAsync(cW1,  d_in[7],  128  * sizeof(float), 0, cudaMemcpyDeviceToDevice, 0);
    cudaMemcpyToSymbolAsync(cb1,  d_in[8],  64   * sizeof(float), 0, cudaMemcpyDeviceToDevice, 0);
    cudaMemcpyToSymbolAsync(cW2,  d_in[9],  2048 * sizeof(float), 0, cudaMemcpyDeviceToDevice, 0);
    cudaMemcpyToSymbolAsync(cb2,  d_in[10], 32   * sizeof(float), 0, cudaMemcpyDeviceToDevice, 0);
    cudaMemcpyToSymbolAsync(cW3,  d_in[11], 2048 * sizeof(float), 0, cudaMemcpyDeviceToDevice, 0);
    cudaMemcpyToSymbolAsync(cb3,  d_in[12], 64   * sizeof(float), 0, cudaMemcpyDeviceToDevice, 0);
    cudaMemcpyToSymbolAsync(cW4,  d_in[13], 64   * sizeof(float), 0, cudaMemcpyDeviceToDevice, 0);
    cudaMemcpyToSymbolAsync(cb4c, d_in[14], 1    * sizeof(float), 0, cudaMemcpyDeviceToDevice, 0);

    k_hist    <<<(E_SUB + 255) / 256, 256>>>(rxn_sub, x, out);               // 0
    k_scan    <<<NB1, 1024>>>();                                             // 1
    k_scatter <<<(E_SUB + 255) / 256, 256>>>(met_sub, rxn_sub, sto_sub);     // 2
    k_rxn     <<<(N_RXN + 127) / 128, 128>>>(log_k);                         // 3 <- profiled
    k_metscale<<<(N_MET + 255) / 256, 256>>>();                              // 4
    k_vscale  <<<(N_RXN + 255) / 256, 256>>>();                              // 5
    k_out     <<<(E_ALL + 255) / 256, 256>>>(met_all, rxn_all, sto_all, out);// 6
}